// round 16
// baseline (speedup 1.0000x reference)
#include <cuda_runtime.h>
#include <cuda_bf16.h>
#include <math.h>
#include <stdint.h>

#define B_   16
#define S_   1024
#define D_   1024
#define U_   512
#define M_   (B_ * S_)          // 16384
#define G3U  (3 * U_)           // 1536
#define NCTA_SCAN 128

// ---------------- static device scratch ----------------
__device__ __nv_bfloat16 g_xn2 [(size_t)M_ * 2 * D_];   // ln out, [row, hi(D)|lo(D)]
__device__ __nv_bfloat16 g_u2  [(size_t)M_ * 2 * U_];   // input proj, split
__device__ float         g_gx  [(size_t)M_ * G3U];      // gate preacts fp32
__device__ __nv_bfloat16 g_y2  [(size_t)M_ * 2 * U_];   // GRU out, split
__device__ __nv_bfloat16 g_win2 [(size_t)U_  * 2 * D_];
__device__ __nv_bfloat16 g_wih2 [(size_t)G3U * 2 * U_];
__device__ __nv_bfloat16 g_wout2[(size_t)D_  * 2 * U_];
__device__ float g_h[2 * U_ * B_];
__device__ unsigned g_cnt4[4 * 32];                     // 4 split counters, 128B apart

// ================= PTX helpers (compute_103-safe) ======
__device__ __forceinline__ uint32_t smem_u32(const void* p) {
  uint32_t a;
  asm("{ .reg .u64 t; cvta.to.shared.u64 t, %1; cvt.u32.u64 %0, t; }" : "=r"(a) : "l"(p));
  return a;
}
__device__ __forceinline__ void cp16(uint32_t dst, const void* src) {
  asm volatile("cp.async.cg.shared.global [%0], [%1], 16;"
               :: "r"(dst), "l"(__cvta_generic_to_global(src)) : "memory");
}
#define CP_COMMIT() asm volatile("cp.async.commit_group;" ::: "memory")
#define CP_WAIT(n)  asm volatile("cp.async.wait_group %0;" :: "n"(n) : "memory")

#define LDSM_X4(r0, r1, r2, r3, a)                                                     \
  asm volatile("ldmatrix.sync.aligned.m8n8.x4.shared.b16 {%0,%1,%2,%3}, [%4];"         \
               : "=r"(r0), "=r"(r1), "=r"(r2), "=r"(r3) : "r"(a))
#define LDSM_X2(r0, r1, a)                                                             \
  asm volatile("ldmatrix.sync.aligned.m8n8.x2.shared.b16 {%0,%1}, [%2];"               \
               : "=r"(r0), "=r"(r1) : "r"(a))
#define MMA_BF16(d, av, bv)                                                            \
  asm volatile("mma.sync.aligned.m16n8k16.row.col.f32.bf16.bf16.f32 "                  \
               "{%0,%1,%2,%3}, {%4,%5,%6,%7}, {%8,%9}, {%0,%1,%2,%3};"                 \
               : "+f"((d)[0]), "+f"((d)[1]), "+f"((d)[2]), "+f"((d)[3])                \
               : "r"((av)[0]), "r"((av)[1]), "r"((av)[2]), "r"((av)[3]),               \
                 "r"((bv)[0]), "r"((bv)[1]))

__device__ __forceinline__ unsigned ld_acquire_u32(const unsigned* p) {
  unsigned v;
  asm volatile("ld.acquire.gpu.u32 %0, [%1];" : "=r"(v) : "l"(p));
  return v;
}
__device__ __forceinline__ void red_release_add(unsigned* p, unsigned v) {
  asm volatile("red.release.gpu.add.u32 [%0], %1;" :: "l"(p), "r"(v) : "memory");
}

// ---------------- LayerNorm -> bf16 split ----------------
__global__ __launch_bounds__(256) void ln_kernel(const float* __restrict__ x,
                                                 const float* __restrict__ gamma,
                                                 const float* __restrict__ beta,
                                                 __nv_bfloat16* __restrict__ xn2) {
  const int row = blockIdx.x;
  const int t = threadIdx.x;
  float4 v = reinterpret_cast<const float4*>(x + (size_t)row * D_)[t];
  float s  = v.x + v.y + v.z + v.w;
  float ss = v.x * v.x + v.y * v.y + v.z * v.z + v.w * v.w;
#pragma unroll
  for (int o = 16; o > 0; o >>= 1) {
    s  += __shfl_xor_sync(0xffffffffu, s, o);
    ss += __shfl_xor_sync(0xffffffffu, ss, o);
  }
  __shared__ float rs[8], rss[8], stat[2];
  const int wid = t >> 5, lane = t & 31;
  if (lane == 0) { rs[wid] = s; rss[wid] = ss; }
  __syncthreads();
  if (wid == 0) {
    s  = (lane < 8) ? rs[lane]  : 0.f;
    ss = (lane < 8) ? rss[lane] : 0.f;
#pragma unroll
    for (int o = 4; o > 0; o >>= 1) {
      s  += __shfl_xor_sync(0xffffffffu, s, o);
      ss += __shfl_xor_sync(0xffffffffu, ss, o);
    }
    if (lane == 0) {
      float mu = s * (1.f / D_);
      float var = ss * (1.f / D_) - mu * mu;
      stat[0] = mu; stat[1] = rsqrtf(var + 1e-5f);
    }
  }
  __syncthreads();
  const float mu = stat[0], rstd = stat[1];
  float4 g = reinterpret_cast<const float4*>(gamma)[t];
  float4 b = reinterpret_cast<const float4*>(beta)[t];
  float o[4];
  o[0] = (v.x - mu) * rstd * g.x + b.x;
  o[1] = (v.y - mu) * rstd * g.y + b.y;
  o[2] = (v.z - mu) * rstd * g.z + b.z;
  o[3] = (v.w - mu) * rstd * g.w + b.w;
  __nv_bfloat16* hi = xn2 + (size_t)row * (2 * D_) + 4 * t;
  __nv_bfloat16* lo = hi + D_;
#pragma unroll
  for (int j = 0; j < 4; ++j) {
    __nv_bfloat16 h = __float2bfloat16(o[j]);
    hi[j] = h;
    lo[j] = __float2bfloat16(o[j] - __bfloat162float(h));
  }
}

// ---------------- weight split conversion ----------------
__global__ void wconv(const float* __restrict__ w, __nv_bfloat16* __restrict__ w2,
                      int K, int total) {
  int i = blockIdx.x * blockDim.x + threadIdx.x;
  if (i >= total) return;
  int r = i / K, c = i - r * K;
  float v = w[i];
  __nv_bfloat16 h = __float2bfloat16(v);
  w2[(size_t)r * 2 * K + c] = h;
  w2[(size_t)r * 2 * K + K + c] = __float2bfloat16(v - __bfloat162float(h));
}

// ---------------- mma.sync bf16-split NT GEMM (unchanged, proven) ----------------
#define STG 3
#define STAGE_B 16384

__device__ __forceinline__ uint32_t sw_off(int r, int cb) {
  return (uint32_t)(r * 64 + ((cb ^ ((r >> 1) & 3)) << 4));
}

template <int MODE>
__global__ __launch_bounds__(256) void gemm_mma(const __nv_bfloat16* __restrict__ A2,
                                                const __nv_bfloat16* __restrict__ W2,
                                                const float* __restrict__ bias,
                                                const float* __restrict__ resid,
                                                float* __restrict__ Cf,
                                                __nv_bfloat16* __restrict__ C2,
                                                int N, int K) {
  __shared__ __align__(128) char smem[STG * STAGE_B];
  const uint32_t sbase = smem_u32(smem);
  const int tid = threadIdx.x;
  const int warp = tid >> 5, lane = tid & 31;
  const int wm = warp >> 2, wn = warp & 3;
  const int m0 = blockIdx.x * 128;
  const int n0 = blockIdx.y * 128;
  const int lda = 2 * K;
  const int cpp = K / 32;
  const int nc = 3 * cpp;

  const __nv_bfloat16* Ab = A2 + (size_t)m0 * lda;
  const __nv_bfloat16* Wb = W2 + (size_t)n0 * lda;

  const int lr = tid >> 2;
  const int lc = tid & 3;

  auto load_tile = [&](int c) {
    const int p = c / cpp;
    const int kc = (c - p * cpp) * 32;
    const int acol = ((p == 1) ? K : 0) + kc;
    const int bcol = ((p == 2) ? K : 0) + kc;
    const uint32_t sa = sbase + (c % STG) * STAGE_B;
    const uint32_t sb = sa + 8192;
#pragma unroll
    for (int q = 0; q < 2; ++q) {
      int r = q * 64 + lr;
      cp16(sa + sw_off(r, lc), (const char*)(Ab + (size_t)r * lda + acol) + (lc << 4));
      cp16(sb + sw_off(r, lc), (const char*)(Wb + (size_t)r * lda + bcol) + (lc << 4));
    }
  };

  float acc[4][4][4];
#pragma unroll
  for (int i = 0; i < 4; ++i)
#pragma unroll
    for (int j = 0; j < 4; ++j)
#pragma unroll
      for (int e = 0; e < 4; ++e) acc[i][j][e] = 0.f;

  const int rA = (lane < 16) ? lane : (lane - 16);
  const int hA = (lane < 16) ? 0 : 1;
  const int selA = (rA >> 1) & 3;
  const int l15 = lane & 15;
  const int rB = l15 & 7;
  const int hB = (l15 >> 3) & 1;
  const int selB = (rB >> 1) & 3;

  load_tile(0); CP_COMMIT();
  load_tile(1); CP_COMMIT();

  for (int i = 0; i < nc; ++i) {
    if (i + 2 < nc) load_tile(i + 2);
    CP_COMMIT();
    CP_WAIT(2);
    __syncthreads();

    const uint32_t sa = sbase + (i % STG) * STAGE_B;
    const uint32_t sb = sa + 8192;
#pragma unroll
    for (int ks = 0; ks < 2; ++ks) {
      uint32_t Af[4][4], Bf[4][2];
#pragma unroll
      for (int mt = 0; mt < 4; ++mt) {
        int row = wm * 64 + mt * 16 + rA;
        uint32_t a = sa + (uint32_t)(row * 64) + (uint32_t)(((ks * 2 + hA) ^ selA) << 4);
        LDSM_X4(Af[mt][0], Af[mt][1], Af[mt][2], Af[mt][3], a);
      }
#pragma unroll
      for (int nt = 0; nt < 4; ++nt) {
        int row = wn * 32 + nt * 8 + rB;
        uint32_t a = sb + (uint32_t)(row * 64) + (uint32_t)(((ks * 2 + hB) ^ selB) << 4);
        LDSM_X2(Bf[nt][0], Bf[nt][1], a);
      }
#pragma unroll
      for (int mt = 0; mt < 4; ++mt)
#pragma unroll
        for (int nt = 0; nt < 4; ++nt) MMA_BF16(acc[mt][nt], Af[mt], Bf[nt]);
    }
    __syncthreads();
  }

  const int g = lane >> 2, t4 = lane & 3;
#pragma unroll
  for (int mt = 0; mt < 4; ++mt) {
#pragma unroll
    for (int nt = 0; nt < 4; ++nt) {
      int col = n0 + wn * 32 + nt * 8 + t4 * 2;
      float bx = __ldg(bias + col), by = __ldg(bias + col + 1);
#pragma unroll
      for (int hrow = 0; hrow < 2; ++hrow) {
        int row = m0 + wm * 64 + mt * 16 + g + hrow * 8;
        float vx = acc[mt][nt][hrow * 2 + 0] + bx;
        float vy = acc[mt][nt][hrow * 2 + 1] + by;
        if (MODE == 2) {
          __nv_bfloat16 hx = __float2bfloat16(vx);
          __nv_bfloat16 hy = __float2bfloat16(vy);
          size_t rb = (size_t)row * 2 * N;
          C2[rb + col] = hx;
          C2[rb + col + 1] = hy;
          C2[rb + N + col] = __float2bfloat16(vx - __bfloat162float(hx));
          C2[rb + N + col + 1] = __float2bfloat16(vy - __bfloat162float(hy));
        } else {
          if (MODE == 1) {
            const float2 r2 = *reinterpret_cast<const float2*>(resid + (size_t)row * N + col);
            vx += r2.x; vy += r2.y;
          }
          float2 o; o.x = vx; o.y = vy;
          *reinterpret_cast<float2*>(Cf + (size_t)row * N + col) = o;
        }
      }
    }
  }
}

// ---------------- init: zero h buffer 0 and the split counters ----------------
__global__ void init_kernel() {
  int i = blockIdx.x * blockDim.x + threadIdx.x;
  if (i < U_ * B_) g_h[i] = 0.f;
  if (i < 4 * 32) g_cnt4[i] = 0u;
}

// ---------------- persistent GRU scan (R15 + warp-local staging + split counters) --
// dynamic SMEM (floats): sH 512*24=12288, sP 12*16*17=3264, sB 16
#define SCAN_SMEM_FLOATS (12288 + 3264 + 16)

__global__ __launch_bounds__(256, 1) void scan_kernel(const float* __restrict__ gx,
                                                      const float* __restrict__ w_hh,
                                                      const float* __restrict__ b_hh,
                                                      __nv_bfloat16* __restrict__ y2,
                                                      float* __restrict__ h_last) {
  extern __shared__ float smemf[];
  float* sH = smemf;
  float* sP = sH + 12288;
  float* sB = sP + 3264;

  const int tid = threadIdx.x;
  const int bu0 = blockIdx.x * 4;      // first unit this CTA owns
  const int ks = tid >> 4;             // k-slice 0..15 (32 k each); warp w holds 2w,2w+1
  const int grp = tid & 15;
  const int rg = grp >> 2;             // row group: rows rg*3 .. rg*3+2
  const int bg = grp & 3;              // batch group: batches bg*4 .. +3

  // warp-local staging: warp w stages units [64w, 64w+64) — exactly what it consumes
  const int su0 = (tid >> 5) * 64 + (tid & 31);

  // ---- load this thread's w_hh slice into registers: 3 rows x 32 k ----
  float wreg[3][32];
#pragma unroll
  for (int r = 0; r < 3; ++r) {
    const int lrow = rg * 3 + r;             // local row 0..11 = gate*4 + ui
    const int gate = lrow >> 2, ui = lrow & 3;
    const float4* wp = reinterpret_cast<const float4*>(
        w_hh + ((size_t)(gate * U_ + bu0 + ui)) * U_ + ks * 32);
#pragma unroll
    for (int q = 0; q < 8; ++q) {
      float4 v = __ldg(wp + q);
      wreg[r][q * 4 + 0] = v.x; wreg[r][q * 4 + 1] = v.y;
      wreg[r][q * 4 + 2] = v.z; wreg[r][q * 4 + 3] = v.w;
    }
  }
  if (tid < 12) sB[tid] = b_hh[(tid >> 2) * U_ + bu0 + (tid & 3)];

  // epilogue gx base (threads 0..63: b = tid&15, ui = tid>>4)
  const float* gxp = gx + (size_t)(tid & 15) * S_ * G3U + (size_t)(bu0 + (tid >> 4));

  for (int t = 0; t < S_; ++t) {
    const int par = t & 1;

    // ---- prefetch gx for this step (consumed in the epilogue) ----
    float xr = 0.f, xz = 0.f, xnv = 0.f;
    if (tid < 64) {
      const size_t o = (size_t)t * G3U;
      xr  = __ldg(gxp + o);
      xz  = __ldg(gxp + o + U_);
      xnv = __ldg(gxp + o + 2 * U_);
    }

    // ---- warp-local stage: each warp stages its own 64 units, then syncwarp ----
    const float* hsrc = g_h + par * (U_ * B_);
#pragma unroll
    for (int p = 0; p < 2; ++p) {
      int u = su0 + p * 32;
      const float4* s4 = reinterpret_cast<const float4*>(hsrc + u * B_);
      float4 v0 = __ldcg(s4 + 0);
      float4 v1 = __ldcg(s4 + 1);
      float4 v2 = __ldcg(s4 + 2);
      float4 v3 = __ldcg(s4 + 3);
      float4* d4 = reinterpret_cast<float4*>(sH + u * 24);
      d4[0] = v0; d4[1] = v1; d4[2] = v2; d4[3] = v3;
    }
    __syncwarp();

    // ---- partial gh: 3 rows x 4 batches over a 32-wide k slice (w in regs) ----
    float acc[3][4];
#pragma unroll
    for (int r = 0; r < 3; ++r)
#pragma unroll
      for (int bb = 0; bb < 4; ++bb) acc[r][bb] = 0.f;

#pragma unroll
    for (int kq = 0; kq < 8; ++kq) {
#pragma unroll
      for (int j = 0; j < 4; ++j) {
        const int kk = kq * 4 + j;
        float4 h = *reinterpret_cast<const float4*>(sH + (ks * 32 + kk) * 24 + bg * 4);
        const float w0 = wreg[0][kk], w1 = wreg[1][kk], w2 = wreg[2][kk];
        acc[0][0] += w0 * h.x; acc[0][1] += w0 * h.y;
        acc[0][2] += w0 * h.z; acc[0][3] += w0 * h.w;
        acc[1][0] += w1 * h.x; acc[1][1] += w1 * h.y;
        acc[1][2] += w1 * h.z; acc[1][3] += w1 * h.w;
        acc[2][0] += w2 * h.x; acc[2][1] += w2 * h.y;
        acc[2][2] += w2 * h.z; acc[2][3] += w2 * h.w;
      }
    }
#pragma unroll
    for (int r = 0; r < 3; ++r) {
      int lrow = rg * 3 + r;
#pragma unroll
      for (int bb = 0; bb < 4; ++bb)
        sP[(lrow * 16 + bg * 4 + bb) * 17 + ks] = acc[r][bb];
    }
    __syncthreads();

    // ---- reduce + gate epilogue: 64 threads = (unit 0..3) x (batch 0..15) ----
    if (tid < 64) {
      const int ui = tid >> 4;
      const int b = tid & 15;
      const int u = bu0 + ui;
      float gh[3];
#pragma unroll
      for (int g = 0; g < 3; ++g) {
        const float* p = sP + ((g * 4 + ui) * 16 + b) * 17;
        float s0 = (p[0] + p[1]) + (p[2] + p[3]);
        float s1 = (p[4] + p[5]) + (p[6] + p[7]);
        float s2 = (p[8] + p[9]) + (p[10] + p[11]);
        float s3 = (p[12] + p[13]) + (p[14] + p[15]);
        gh[g] = ((s0 + s1) + (s2 + s3)) + sB[g * 4 + ui];
      }
      float r = 1.f / (1.f + expf(-(xr + gh[0])));
      float z = 1.f / (1.f + expf(-(xz + gh[1])));
      float n = tanhf(xnv + r * gh[2]);
      float hp = sH[u * 24 + b];
      float hn = (1.f - z) * n + z * hp;
      __stcg(g_h + (par ^ 1) * (U_ * B_) + u * B_ + b, hn);
      size_t r2 = ((size_t)b * S_ + t) * (size_t)(2 * U_);
      __nv_bfloat16 hi = __float2bfloat16(hn);
      y2[r2 + u] = hi;
      y2[r2 + U_ + u] = __float2bfloat16(hn - __bfloat162float(hi));
      if (t == S_ - 1) h_last[b * U_ + u] = hn;

      // early release: only the 2 epilogue warps need to have finished h writes
      asm volatile("bar.sync 1, 64;" ::: "memory");
      if (tid == 0 && t != S_ - 1)
        red_release_add(&g_cnt4[(blockIdx.x & 3) * 32], 1u);
    }

    // ---- grid barrier wait: poll the 4 split counters, sum vs 128*(t+1) ----
    if (t != S_ - 1) {
      if (tid == 0) {
        const unsigned target = (unsigned)(t + 1) * (unsigned)NCTA_SCAN;
        for (;;) {
          unsigned v = ld_acquire_u32(&g_cnt4[0]) + ld_acquire_u32(&g_cnt4[32]) +
                       ld_acquire_u32(&g_cnt4[64]) + ld_acquire_u32(&g_cnt4[96]);
          if (v >= target) break;
        }
      }
      __syncthreads();
    }
  }
}

// ---------------- launch ----------------
extern "C" void kernel_launch(void* const* d_in, const int* in_sizes, int n_in,
                              void* d_out, int out_size) {
  const float* x     = (const float*)d_in[0];
  const float* gamma = (const float*)d_in[1];
  const float* beta  = (const float*)d_in[2];
  const float* w_in  = (const float*)d_in[3];
  const float* b_in  = (const float*)d_in[4];
  const float* w_ih  = (const float*)d_in[5];
  const float* w_hh  = (const float*)d_in[6];
  const float* b_ih  = (const float*)d_in[7];
  const float* b_hh  = (const float*)d_in[8];
  const float* w_out = (const float*)d_in[9];
  const float* b_out = (const float*)d_in[10];
  float* out = (float*)d_out;

  __nv_bfloat16 *xn2, *u2, *y2, *win2, *wih2, *wout2;
  float* gx;
  cudaGetSymbolAddress((void**)&xn2,   g_xn2);
  cudaGetSymbolAddress((void**)&u2,    g_u2);
  cudaGetSymbolAddress((void**)&y2,    g_y2);
  cudaGetSymbolAddress((void**)&win2,  g_win2);
  cudaGetSymbolAddress((void**)&wih2,  g_wih2);
  cudaGetSymbolAddress((void**)&wout2, g_wout2);
  cudaGetSymbolAddress((void**)&gx,    g_gx);

  cudaFuncSetAttribute(scan_kernel, cudaFuncAttributeMaxDynamicSharedMemorySize,
                       SCAN_SMEM_FLOATS * 4);

  ln_kernel<<<M_, 256>>>(x, gamma, beta, xn2);
  wconv<<<(U_ * D_ + 255) / 256, 256>>>(w_in, win2, D_, U_ * D_);
  wconv<<<(G3U * U_ + 255) / 256, 256>>>(w_ih, wih2, U_, G3U * U_);
  wconv<<<(D_ * U_ + 255) / 256, 256>>>(w_out, wout2, U_, D_ * U_);

  // u2 = split( xn @ w_in^T + b_in )
  gemm_mma<2><<<dim3(M_ / 128, U_ / 128), 256>>>(xn2, win2, b_in, nullptr,
                                                 nullptr, u2, U_, D_);
  // gx = u @ w_ih^T + b_ih (fp32)
  gemm_mma<0><<<dim3(M_ / 128, G3U / 128), 256>>>(u2, wih2, b_ih, nullptr,
                                                  gx, nullptr, G3U, U_);
  init_kernel<<<32, 256>>>();
  scan_kernel<<<NCTA_SCAN, 256, SCAN_SMEM_FLOATS * 4>>>(gx, w_hh, b_hh, y2,
                                                        out + (size_t)M_ * D_);
  // out = x + y @ w_out^T + b_out
  gemm_mma<1><<<dim3(M_ / 128, D_ / 128), 256>>>(y2, wout2, b_out, x,
                                                 out, nullptr, D_, U_);
}

// round 17
// speedup vs baseline: 1.8151x; 1.8151x over previous
#include <cuda_runtime.h>
#include <cuda_bf16.h>
#include <math.h>
#include <stdint.h>

#define B_   16
#define S_   1024
#define D_   1024
#define U_   512
#define M_   (B_ * S_)          // 16384
#define G3U  (3 * U_)           // 1536
#define NCTA_SCAN 128

// ---------------- static device scratch ----------------
__device__ __nv_bfloat16 g_xn2 [(size_t)M_ * 2 * D_];   // ln out, [row, hi(D)|lo(D)]
__device__ __nv_bfloat16 g_u2  [(size_t)M_ * 2 * U_];   // input proj, split
__device__ float         g_gx  [(size_t)M_ * G3U];      // gate preacts fp32
__device__ __nv_bfloat16 g_y2  [(size_t)M_ * 2 * U_];   // GRU out, split
__device__ __nv_bfloat16 g_win2 [(size_t)U_  * 2 * D_];
__device__ __nv_bfloat16 g_wih2 [(size_t)G3U * 2 * U_];
__device__ __nv_bfloat16 g_wout2[(size_t)D_  * 2 * U_];
__device__ float g_h[2 * U_ * B_];
__device__ unsigned g_cnt;                              // central barrier counter

// ================= PTX helpers (compute_103-safe) ======
__device__ __forceinline__ uint32_t smem_u32(const void* p) {
  uint32_t a;
  asm("{ .reg .u64 t; cvta.to.shared.u64 t, %1; cvt.u32.u64 %0, t; }" : "=r"(a) : "l"(p));
  return a;
}
__device__ __forceinline__ void cp16(uint32_t dst, const void* src) {
  asm volatile("cp.async.cg.shared.global [%0], [%1], 16;"
               :: "r"(dst), "l"(__cvta_generic_to_global(src)) : "memory");
}
#define CP_COMMIT() asm volatile("cp.async.commit_group;" ::: "memory")
#define CP_WAIT(n)  asm volatile("cp.async.wait_group %0;" :: "n"(n) : "memory")

#define LDSM_X4(r0, r1, r2, r3, a)                                                     \
  asm volatile("ldmatrix.sync.aligned.m8n8.x4.shared.b16 {%0,%1,%2,%3}, [%4];"         \
               : "=r"(r0), "=r"(r1), "=r"(r2), "=r"(r3) : "r"(a))
#define LDSM_X2(r0, r1, a)                                                             \
  asm volatile("ldmatrix.sync.aligned.m8n8.x2.shared.b16 {%0,%1}, [%2];"               \
               : "=r"(r0), "=r"(r1) : "r"(a))
#define MMA_BF16(d, av, bv)                                                            \
  asm volatile("mma.sync.aligned.m16n8k16.row.col.f32.bf16.bf16.f32 "                  \
               "{%0,%1,%2,%3}, {%4,%5,%6,%7}, {%8,%9}, {%0,%1,%2,%3};"                 \
               : "+f"((d)[0]), "+f"((d)[1]), "+f"((d)[2]), "+f"((d)[3])                \
               : "r"((av)[0]), "r"((av)[1]), "r"((av)[2]), "r"((av)[3]),               \
                 "r"((bv)[0]), "r"((bv)[1]))

__device__ __forceinline__ unsigned ld_acquire_u32(const unsigned* p) {
  unsigned v;
  asm volatile("ld.acquire.gpu.u32 %0, [%1];" : "=r"(v) : "l"(p));
  return v;
}
__device__ __forceinline__ void red_release_add(unsigned* p, unsigned v) {
  asm volatile("red.release.gpu.add.u32 [%0], %1;" :: "l"(p), "r"(v) : "memory");
}

// ---------------- LayerNorm -> bf16 split ----------------
__global__ __launch_bounds__(256) void ln_kernel(const float* __restrict__ x,
                                                 const float* __restrict__ gamma,
                                                 const float* __restrict__ beta,
                                                 __nv_bfloat16* __restrict__ xn2) {
  const int row = blockIdx.x;
  const int t = threadIdx.x;
  float4 v = reinterpret_cast<const float4*>(x + (size_t)row * D_)[t];
  float s  = v.x + v.y + v.z + v.w;
  float ss = v.x * v.x + v.y * v.y + v.z * v.z + v.w * v.w;
#pragma unroll
  for (int o = 16; o > 0; o >>= 1) {
    s  += __shfl_xor_sync(0xffffffffu, s, o);
    ss += __shfl_xor_sync(0xffffffffu, ss, o);
  }
  __shared__ float rs[8], rss[8], stat[2];
  const int wid = t >> 5, lane = t & 31;
  if (lane == 0) { rs[wid] = s; rss[wid] = ss; }
  __syncthreads();
  if (wid == 0) {
    s  = (lane < 8) ? rs[lane]  : 0.f;
    ss = (lane < 8) ? rss[lane] : 0.f;
#pragma unroll
    for (int o = 4; o > 0; o >>= 1) {
      s  += __shfl_xor_sync(0xffffffffu, s, o);
      ss += __shfl_xor_sync(0xffffffffu, ss, o);
    }
    if (lane == 0) {
      float mu = s * (1.f / D_);
      float var = ss * (1.f / D_) - mu * mu;
      stat[0] = mu; stat[1] = rsqrtf(var + 1e-5f);
    }
  }
  __syncthreads();
  const float mu = stat[0], rstd = stat[1];
  float4 g = reinterpret_cast<const float4*>(gamma)[t];
  float4 b = reinterpret_cast<const float4*>(beta)[t];
  float o[4];
  o[0] = (v.x - mu) * rstd * g.x + b.x;
  o[1] = (v.y - mu) * rstd * g.y + b.y;
  o[2] = (v.z - mu) * rstd * g.z + b.z;
  o[3] = (v.w - mu) * rstd * g.w + b.w;
  __nv_bfloat16* hi = xn2 + (size_t)row * (2 * D_) + 4 * t;
  __nv_bfloat16* lo = hi + D_;
#pragma unroll
  for (int j = 0; j < 4; ++j) {
    __nv_bfloat16 h = __float2bfloat16(o[j]);
    hi[j] = h;
    lo[j] = __float2bfloat16(o[j] - __bfloat162float(h));
  }
}

// ---------------- weight split conversion ----------------
__global__ void wconv(const float* __restrict__ w, __nv_bfloat16* __restrict__ w2,
                      int K, int total) {
  int i = blockIdx.x * blockDim.x + threadIdx.x;
  if (i >= total) return;
  int r = i / K, c = i - r * K;
  float v = w[i];
  __nv_bfloat16 h = __float2bfloat16(v);
  w2[(size_t)r * 2 * K + c] = h;
  w2[(size_t)r * 2 * K + K + c] = __float2bfloat16(v - __bfloat162float(h));
}

// ---------------- mma.sync bf16-split NT GEMM (unchanged, proven) ----------------
#define STG 3
#define STAGE_B 16384

__device__ __forceinline__ uint32_t sw_off(int r, int cb) {
  return (uint32_t)(r * 64 + ((cb ^ ((r >> 1) & 3)) << 4));
}

template <int MODE>
__global__ __launch_bounds__(256) void gemm_mma(const __nv_bfloat16* __restrict__ A2,
                                                const __nv_bfloat16* __restrict__ W2,
                                                const float* __restrict__ bias,
                                                const float* __restrict__ resid,
                                                float* __restrict__ Cf,
                                                __nv_bfloat16* __restrict__ C2,
                                                int N, int K) {
  __shared__ __align__(128) char smem[STG * STAGE_B];
  const uint32_t sbase = smem_u32(smem);
  const int tid = threadIdx.x;
  const int warp = tid >> 5, lane = tid & 31;
  const int wm = warp >> 2, wn = warp & 3;
  const int m0 = blockIdx.x * 128;
  const int n0 = blockIdx.y * 128;
  const int lda = 2 * K;
  const int cpp = K / 32;
  const int nc = 3 * cpp;

  const __nv_bfloat16* Ab = A2 + (size_t)m0 * lda;
  const __nv_bfloat16* Wb = W2 + (size_t)n0 * lda;

  const int lr = tid >> 2;
  const int lc = tid & 3;

  auto load_tile = [&](int c) {
    const int p = c / cpp;
    const int kc = (c - p * cpp) * 32;
    const int acol = ((p == 1) ? K : 0) + kc;
    const int bcol = ((p == 2) ? K : 0) + kc;
    const uint32_t sa = sbase + (c % STG) * STAGE_B;
    const uint32_t sb = sa + 8192;
#pragma unroll
    for (int q = 0; q < 2; ++q) {
      int r = q * 64 + lr;
      cp16(sa + sw_off(r, lc), (const char*)(Ab + (size_t)r * lda + acol) + (lc << 4));
      cp16(sb + sw_off(r, lc), (const char*)(Wb + (size_t)r * lda + bcol) + (lc << 4));
    }
  };

  float acc[4][4][4];
#pragma unroll
  for (int i = 0; i < 4; ++i)
#pragma unroll
    for (int j = 0; j < 4; ++j)
#pragma unroll
      for (int e = 0; e < 4; ++e) acc[i][j][e] = 0.f;

  const int rA = (lane < 16) ? lane : (lane - 16);
  const int hA = (lane < 16) ? 0 : 1;
  const int selA = (rA >> 1) & 3;
  const int l15 = lane & 15;
  const int rB = l15 & 7;
  const int hB = (l15 >> 3) & 1;
  const int selB = (rB >> 1) & 3;

  load_tile(0); CP_COMMIT();
  load_tile(1); CP_COMMIT();

  for (int i = 0; i < nc; ++i) {
    if (i + 2 < nc) load_tile(i + 2);
    CP_COMMIT();
    CP_WAIT(2);
    __syncthreads();

    const uint32_t sa = sbase + (i % STG) * STAGE_B;
    const uint32_t sb = sa + 8192;
#pragma unroll
    for (int ks = 0; ks < 2; ++ks) {
      uint32_t Af[4][4], Bf[4][2];
#pragma unroll
      for (int mt = 0; mt < 4; ++mt) {
        int row = wm * 64 + mt * 16 + rA;
        uint32_t a = sa + (uint32_t)(row * 64) + (uint32_t)(((ks * 2 + hA) ^ selA) << 4);
        LDSM_X4(Af[mt][0], Af[mt][1], Af[mt][2], Af[mt][3], a);
      }
#pragma unroll
      for (int nt = 0; nt < 4; ++nt) {
        int row = wn * 32 + nt * 8 + rB;
        uint32_t a = sb + (uint32_t)(row * 64) + (uint32_t)(((ks * 2 + hB) ^ selB) << 4);
        LDSM_X2(Bf[nt][0], Bf[nt][1], a);
      }
#pragma unroll
      for (int mt = 0; mt < 4; ++mt)
#pragma unroll
        for (int nt = 0; nt < 4; ++nt) MMA_BF16(acc[mt][nt], Af[mt], Bf[nt]);
    }
    __syncthreads();
  }

  const int g = lane >> 2, t4 = lane & 3;
#pragma unroll
  for (int mt = 0; mt < 4; ++mt) {
#pragma unroll
    for (int nt = 0; nt < 4; ++nt) {
      int col = n0 + wn * 32 + nt * 8 + t4 * 2;
      float bx = __ldg(bias + col), by = __ldg(bias + col + 1);
#pragma unroll
      for (int hrow = 0; hrow < 2; ++hrow) {
        int row = m0 + wm * 64 + mt * 16 + g + hrow * 8;
        float vx = acc[mt][nt][hrow * 2 + 0] + bx;
        float vy = acc[mt][nt][hrow * 2 + 1] + by;
        if (MODE == 2) {
          __nv_bfloat16 hx = __float2bfloat16(vx);
          __nv_bfloat16 hy = __float2bfloat16(vy);
          size_t rb = (size_t)row * 2 * N;
          C2[rb + col] = hx;
          C2[rb + col + 1] = hy;
          C2[rb + N + col] = __float2bfloat16(vx - __bfloat162float(hx));
          C2[rb + N + col + 1] = __float2bfloat16(vy - __bfloat162float(hy));
        } else {
          if (MODE == 1) {
            const float2 r2 = *reinterpret_cast<const float2*>(resid + (size_t)row * N + col);
            vx += r2.x; vy += r2.y;
          }
          float2 o; o.x = vx; o.y = vy;
          *reinterpret_cast<float2*>(Cf + (size_t)row * N + col) = o;
        }
      }
    }
  }
}

// ---------------- init: zero h buffer 0 and the barrier counter ----------------
__global__ void init_kernel() {
  int i = blockIdx.x * blockDim.x + threadIdx.x;
  if (i < U_ * B_) g_h[i] = 0.f;
  if (i == 0) g_cnt = 0u;
}

// ---------------- persistent GRU scan (R15 base + concurrent poll by warp 7) ----
// dynamic SMEM (floats): sH 512*24=12288, sP 12*16*17=3264, sB 16
#define SCAN_SMEM_FLOATS (12288 + 3264 + 16)

__global__ __launch_bounds__(256, 1) void scan_kernel(const float* __restrict__ gx,
                                                      const float* __restrict__ w_hh,
                                                      const float* __restrict__ b_hh,
                                                      __nv_bfloat16* __restrict__ y2,
                                                      float* __restrict__ h_last) {
  extern __shared__ float smemf[];
  float* sH = smemf;
  float* sP = sH + 12288;
  float* sB = sP + 3264;

  const int tid = threadIdx.x;
  const int bu0 = blockIdx.x * 4;      // first unit this CTA owns
  const int ks = tid >> 4;             // k-slice 0..15 (32 k each)
  const int grp = tid & 15;
  const int rg = grp >> 2;             // row group: rows rg*3 .. rg*3+2
  const int bg = grp & 3;              // batch group: batches bg*4 .. +3

  // ---- load this thread's w_hh slice into registers: 3 rows x 32 k ----
  float wreg[3][32];
#pragma unroll
  for (int r = 0; r < 3; ++r) {
    const int lrow = rg * 3 + r;             // local row 0..11 = gate*4 + ui
    const int gate = lrow >> 2, ui = lrow & 3;
    const float4* wp = reinterpret_cast<const float4*>(
        w_hh + ((size_t)(gate * U_ + bu0 + ui)) * U_ + ks * 32);
#pragma unroll
    for (int q = 0; q < 8; ++q) {
      float4 v = __ldg(wp + q);
      wreg[r][q * 4 + 0] = v.x; wreg[r][q * 4 + 1] = v.y;
      wreg[r][q * 4 + 2] = v.z; wreg[r][q * 4 + 3] = v.w;
    }
  }
  if (tid < 12) sB[tid] = b_hh[(tid >> 2) * U_ + bu0 + (tid & 3)];

  // epilogue gx base (threads 0..63: b = tid&15, ui = tid>>4)
  const float* gxp = gx + (size_t)(tid & 15) * S_ * G3U + (size_t)(bu0 + (tid >> 4));

  for (int t = 0; t < S_; ++t) {
    const int par = t & 1;

    // ---- prefetch gx for this step (consumed in the epilogue) ----
    float xr = 0.f, xz = 0.f, xnv = 0.f;
    if (tid < 64) {
      const size_t o = (size_t)t * G3U;
      xr  = __ldg(gxp + o);
      xz  = __ldg(gxp + o + U_);
      xnv = __ldg(gxp + o + 2 * U_);
    }

    // ---- stage full h into SMEM (transposed to [u][b], stride 24) ----
    const float* hsrc = g_h + par * (U_ * B_);
#pragma unroll
    for (int p = 0; p < 2; ++p) {
      int u = p * 256 + tid;
      const float4* s4 = reinterpret_cast<const float4*>(hsrc + u * B_);
      float4 v0 = __ldcg(s4 + 0);
      float4 v1 = __ldcg(s4 + 1);
      float4 v2 = __ldcg(s4 + 2);
      float4 v3 = __ldcg(s4 + 3);
      float4* d4 = reinterpret_cast<float4*>(sH + u * 24);
      d4[0] = v0; d4[1] = v1; d4[2] = v2; d4[3] = v3;
    }
    __syncthreads();

    // ---- partial gh: 3 rows x 4 batches over a 32-wide k slice (w in regs) ----
    float acc[3][4];
#pragma unroll
    for (int r = 0; r < 3; ++r)
#pragma unroll
      for (int bb = 0; bb < 4; ++bb) acc[r][bb] = 0.f;

#pragma unroll
    for (int kq = 0; kq < 8; ++kq) {
#pragma unroll
      for (int j = 0; j < 4; ++j) {
        const int kk = kq * 4 + j;
        float4 h = *reinterpret_cast<const float4*>(sH + (ks * 32 + kk) * 24 + bg * 4);
        const float w0 = wreg[0][kk], w1 = wreg[1][kk], w2 = wreg[2][kk];
        acc[0][0] += w0 * h.x; acc[0][1] += w0 * h.y;
        acc[0][2] += w0 * h.z; acc[0][3] += w0 * h.w;
        acc[1][0] += w1 * h.x; acc[1][1] += w1 * h.y;
        acc[1][2] += w1 * h.z; acc[1][3] += w1 * h.w;
        acc[2][0] += w2 * h.x; acc[2][1] += w2 * h.y;
        acc[2][2] += w2 * h.z; acc[2][3] += w2 * h.w;
      }
    }
#pragma unroll
    for (int r = 0; r < 3; ++r) {
      int lrow = rg * 3 + r;
#pragma unroll
      for (int bb = 0; bb < 4; ++bb)
        sP[(lrow * 16 + bg * 4 + bb) * 17 + ks] = acc[r][bb];
    }
    __syncthreads();

    // ---- reduce + gate epilogue: 64 threads = (unit 0..3) x (batch 0..15) ----
    if (tid < 64) {
      const int ui = tid >> 4;
      const int b = tid & 15;
      const int u = bu0 + ui;
      float gh[3];
#pragma unroll
      for (int g = 0; g < 3; ++g) {
        const float* p = sP + ((g * 4 + ui) * 16 + b) * 17;
        float s0 = (p[0] + p[1]) + (p[2] + p[3]);
        float s1 = (p[4] + p[5]) + (p[6] + p[7]);
        float s2 = (p[8] + p[9]) + (p[10] + p[11]);
        float s3 = (p[12] + p[13]) + (p[14] + p[15]);
        gh[g] = ((s0 + s1) + (s2 + s3)) + sB[g * 4 + ui];
      }
      float r = 1.f / (1.f + expf(-(xr + gh[0])));
      float z = 1.f / (1.f + expf(-(xz + gh[1])));
      float n = tanhf(xnv + r * gh[2]);
      float hp = sH[u * 24 + b];
      float hn = (1.f - z) * n + z * hp;
      __stcg(g_h + (par ^ 1) * (U_ * B_) + u * B_ + b, hn);
      size_t r2 = ((size_t)b * S_ + t) * (size_t)(2 * U_);
      __nv_bfloat16 hi = __float2bfloat16(hn);
      y2[r2 + u] = hi;
      y2[r2 + U_ + u] = __float2bfloat16(hn - __bfloat162float(hi));
      if (t == S_ - 1) h_last[b * U_ + u] = hn;

      // early release: only the 2 epilogue warps need to have finished h writes
      asm volatile("bar.sync 1, 64;" ::: "memory");
      if (tid == 0 && t != S_ - 1) red_release_add(&g_cnt, 1u);
    }

    // ---- grid barrier wait: warp-7 thread polls CONCURRENTLY with the epilogue ----
    if (t != S_ - 1) {
      if (tid == 255) {
        const unsigned target = (unsigned)(t + 1) * (unsigned)gridDim.x;
        unsigned v = ld_acquire_u32(&g_cnt);
        while (v < target) v = ld_acquire_u32(&g_cnt);
      }
      __syncthreads();
    }
  }
}

// ---------------- launch ----------------
extern "C" void kernel_launch(void* const* d_in, const int* in_sizes, int n_in,
                              void* d_out, int out_size) {
  const float* x     = (const float*)d_in[0];
  const float* gamma = (const float*)d_in[1];
  const float* beta  = (const float*)d_in[2];
  const float* w_in  = (const float*)d_in[3];
  const float* b_in  = (const float*)d_in[4];
  const float* w_ih  = (const float*)d_in[5];
  const float* w_hh  = (const float*)d_in[6];
  const float* b_ih  = (const float*)d_in[7];
  const float* b_hh  = (const float*)d_in[8];
  const float* w_out = (const float*)d_in[9];
  const float* b_out = (const float*)d_in[10];
  float* out = (float*)d_out;

  __nv_bfloat16 *xn2, *u2, *y2, *win2, *wih2, *wout2;
  float* gx;
  cudaGetSymbolAddress((void**)&xn2,   g_xn2);
  cudaGetSymbolAddress((void**)&u2,    g_u2);
  cudaGetSymbolAddress((void**)&y2,    g_y2);
  cudaGetSymbolAddress((void**)&win2,  g_win2);
  cudaGetSymbolAddress((void**)&wih2,  g_wih2);
  cudaGetSymbolAddress((void**)&wout2, g_wout2);
  cudaGetSymbolAddress((void**)&gx,    g_gx);

  cudaFuncSetAttribute(scan_kernel, cudaFuncAttributeMaxDynamicSharedMemorySize,
                       SCAN_SMEM_FLOATS * 4);

  ln_kernel<<<M_, 256>>>(x, gamma, beta, xn2);
  wconv<<<(U_ * D_ + 255) / 256, 256>>>(w_in, win2, D_, U_ * D_);
  wconv<<<(G3U * U_ + 255) / 256, 256>>>(w_ih, wih2, U_, G3U * U_);
  wconv<<<(D_ * U_ + 255) / 256, 256>>>(w_out, wout2, U_, D_ * U_);

  // u2 = split( xn @ w_in^T + b_in )
  gemm_mma<2><<<dim3(M_ / 128, U_ / 128), 256>>>(xn2, win2, b_in, nullptr,
                                                 nullptr, u2, U_, D_);
  // gx = u @ w_ih^T + b_ih (fp32)
  gemm_mma<0><<<dim3(M_ / 128, G3U / 128), 256>>>(u2, wih2, b_ih, nullptr,
                                                  gx, nullptr, G3U, U_);
  init_kernel<<<32, 256>>>();
  scan_kernel<<<NCTA_SCAN, 256, SCAN_SMEM_FLOATS * 4>>>(gx, w_hh, b_hh, y2,
                                                        out + (size_t)M_ * D_);
  // out = x + y @ w_out^T + b_out
  gemm_mma<1><<<dim3(M_ / 128, D_ / 128), 256>>>(y2, wout2, b_out, x,
                                                 out, nullptr, D_, U_);
}